// round 3
// baseline (speedup 1.0000x reference)
#include <cuda_runtime.h>
#include <math.h>

// Problem constants (from reference setup_inputs)
#define BB      4
#define NPTS    4096
#define MPTS    4096
#define TSPLIT  4
#define CHUNK   (MPTS / TSPLIT)   // 1024 targets per chunk
#define SBLK    (NPTS / 256)      // 16 source blocks per batch
#define ICP_STEPS 16
#define ICP_TOL   1e-6
#define NMOM    (SBLK * BB)       // 64 mom-capable blocks

// ---------------------------------------------------------------------------
// Device-global scratch (no allocations allowed). All control counters are
// monotonic within a launch and reset to 0 by the final block, so every
// graph replay starts from identical state. Data arrays are write-before-read
// within each launch.
// ---------------------------------------------------------------------------
__device__ float               g_temp[BB * NPTS * 3];
__device__ unsigned long long  g_cand[TSPLIT][BB * NPTS];
__device__ float               g_part[BB][SBLK][16];
__device__ float               g_Rt[BB][12];
__device__ double              g_errlast[BB];
__device__ int                 g_done;
__device__ unsigned            g_gen;              // iteration generation
__device__ unsigned            g_momcnt;           // mom-block arrivals (monotonic)
__device__ unsigned            g_grp[BB][SBLK];    // per-group nn arrivals (monotonic)

// ---------------------------------------------------------------------------
__device__ __forceinline__ void xform(const float* Mtx,
                                      float px, float py, float pz,
                                      float& qx, float& qy, float& qz) {
    qx = fmaf(Mtx[0], px, fmaf(Mtx[1], py, fmaf(Mtx[2], pz, Mtx[9])));
    qy = fmaf(Mtx[3], px, fmaf(Mtx[4], py, fmaf(Mtx[5], pz, Mtx[10])));
    qz = fmaf(Mtx[6], px, fmaf(Mtx[7], py, fmaf(Mtx[8], pz, Mtx[11])));
}

__device__ __forceinline__ unsigned int fmono(float f) {
    unsigned int b = __float_as_uint(f);
    return (b & 0x80000000u) ? ~b : (b | 0x80000000u);
}
__device__ __forceinline__ float fmono_inv(unsigned int m) {
    unsigned int b = (m & 0x80000000u) ? (m ^ 0x80000000u) : ~m;
    return __uint_as_float(b);
}

// packed f32x2 helpers (per-half rounding identical to scalar FFMA)
__device__ __forceinline__ unsigned long long pk2(float v) {
    unsigned long long r;
    asm("mov.b64 %0, {%1, %1};" : "=l"(r) : "f"(v));
    return r;
}
__device__ __forceinline__ unsigned long long fma2(unsigned long long a,
                                                   unsigned long long b,
                                                   unsigned long long c) {
    unsigned long long d;
    asm("fma.rn.f32x2 %0, %1, %2, %3;" : "=l"(d) : "l"(a), "l"(b), "l"(c));
    return d;
}
__device__ __forceinline__ void upk2(unsigned long long v, float& lo, float& hi) {
    asm("mov.b64 {%0, %1}, %2;" : "=f"(lo), "=f"(hi) : "l"(v));
}

// ---------------------------------------------------------------------------
// Kabsch from accumulated sums (identical arithmetic to the R2 version).
// ---------------------------------------------------------------------------
__device__ void kabsch_sums(const double* S, float* Rt) {
    const double invN = 1.0 / (double)NPTS;
    double cs[3] = { S[0] * invN, S[1] * invN, S[2] * invN };
    double ct[3] = { S[3] * invN, S[4] * invN, S[5] * invN };

    float H[3][3];
    for (int i = 0; i < 3; ++i)
        for (int j = 0; j < 3; ++j)
            H[i][j] = (float)(S[6 + 3 * i + j] - (double)NPTS * cs[i] * ct[j]);

    float A[3][3];
    for (int i = 0; i < 3; ++i)
        for (int j = 0; j < 3; ++j)
            A[i][j] = H[0][i] * H[0][j] + H[1][i] * H[1][j] + H[2][i] * H[2][j];

    float V[3][3] = { {1,0,0},{0,1,0},{0,0,1} };
    const float diagmag = fabsf(A[0][0]) + fabsf(A[1][1]) + fabsf(A[2][2]);
    const float offeps  = diagmag * 1e-9f;
    for (int sweep = 0; sweep < 8; ++sweep) {
        const float off = fabsf(A[0][1]) + fabsf(A[0][2]) + fabsf(A[1][2]);
        if (off <= offeps) break;
        for (int pq = 0; pq < 3; ++pq) {
            const int p = (pq == 2) ? 1 : 0;
            const int q = (pq == 0) ? 1 : 2;
            const float apq = A[p][q];
            if (fabsf(apq) <= 0.0f) continue;
            const float theta = (A[q][q] - A[p][p]) / (2.0f * apq);
            const float tt = ((theta >= 0.0f) ? 1.0f : -1.0f) /
                             (fabsf(theta) + sqrtf(theta * theta + 1.0f));
            const float c = rsqrtf(tt * tt + 1.0f);
            const float s = tt * c;
            for (int k = 0; k < 3; ++k) { float a1 = A[p][k], a2 = A[q][k];
                A[p][k] = c * a1 - s * a2; A[q][k] = s * a1 + c * a2; }
            for (int k = 0; k < 3; ++k) { float a1 = A[k][p], a2 = A[k][q];
                A[k][p] = c * a1 - s * a2; A[k][q] = s * a1 + c * a2; }
            for (int k = 0; k < 3; ++k) { float v1 = V[k][p], v2 = V[k][q];
                V[k][p] = c * v1 - s * v2; V[k][q] = s * v1 + c * v2; }
        }
    }

    int id[3] = { 0, 1, 2 };
    float w[3] = { A[0][0], A[1][1], A[2][2] };
    if (w[id[0]] < w[id[1]]) { int t0 = id[0]; id[0] = id[1]; id[1] = t0; }
    if (w[id[0]] < w[id[2]]) { int t0 = id[0]; id[0] = id[2]; id[2] = t0; }
    if (w[id[1]] < w[id[2]]) { int t0 = id[1]; id[1] = id[2]; id[2] = t0; }

    float v1[3], v2[3], v3[3];
    for (int k = 0; k < 3; ++k) { v1[k] = V[k][id[0]]; v2[k] = V[k][id[1]]; v3[k] = V[k][id[2]]; }

    float u1[3], u2[3], u3[3];
    for (int i = 0; i < 3; ++i) u1[i] = H[i][0] * v1[0] + H[i][1] * v1[1] + H[i][2] * v1[2];
    {
        float n1 = u1[0]*u1[0] + u1[1]*u1[1] + u1[2]*u1[2];
        float r = (n1 > 0.0f) ? rsqrtf(n1) : 0.0f;
        u1[0] *= r; u1[1] *= r; u1[2] *= r;
    }
    for (int i = 0; i < 3; ++i) u2[i] = H[i][0] * v2[0] + H[i][1] * v2[1] + H[i][2] * v2[2];
    {
        float pr = u1[0]*u2[0] + u1[1]*u2[1] + u1[2]*u2[2];
        u2[0] -= pr * u1[0]; u2[1] -= pr * u1[1]; u2[2] -= pr * u1[2];
        float n2 = u2[0]*u2[0] + u2[1]*u2[1] + u2[2]*u2[2];
        float r = (n2 > 0.0f) ? rsqrtf(n2) : 0.0f;
        u2[0] *= r; u2[1] *= r; u2[2] *= r;
    }
    u3[0] = u1[1]*u2[2] - u1[2]*u2[1];
    u3[1] = u1[2]*u2[0] - u1[0]*u2[2];
    u3[2] = u1[0]*u2[1] - u1[1]*u2[0];

    const float d =
        v1[0] * (v2[1]*v3[2] - v2[2]*v3[1]) -
        v1[1] * (v2[0]*v3[2] - v2[2]*v3[0]) +
        v1[2] * (v2[0]*v3[1] - v2[1]*v3[0]);

    float R[9];
    for (int i = 0; i < 3; ++i)
        for (int j = 0; j < 3; ++j)
            R[3 * i + j] = v1[i]*u1[j] + v2[i]*u2[j] + d * v3[i]*u3[j];
    for (int k = 0; k < 9; ++k) Rt[k] = R[k];
    for (int i = 0; i < 3; ++i)
        Rt[9 + i] = (float)ct[i] - (R[3*i]*(float)cs[0] + R[3*i+1]*(float)cs[1]
                                    + R[3*i+2]*(float)cs[2]);
}

// ---------------------------------------------------------------------------
// Block-wide deterministic reduction of 16 quantities -> g_part[b][blk][*]
// ---------------------------------------------------------------------------
__device__ __forceinline__ void block_reduce16(float wsum[8][16],
                                               const float v[16], int b, int blk) {
    const int lane = threadIdx.x & 31, wid = threadIdx.x >> 5;
#pragma unroll
    for (int q = 0; q < 16; ++q) {
        float r = v[q];
#pragma unroll
        for (int o = 16; o > 0; o >>= 1) r += __shfl_down_sync(0xffffffffu, r, o);
        if (lane == 0) wsum[wid][q] = r;
    }
    __syncthreads();
    if (threadIdx.x < 16) {
        float acc = 0.f;
#pragma unroll
        for (int w = 0; w < 8; ++w) acc += wsum[w][threadIdx.x];
        g_part[b][blk][threadIdx.x] = acc;
    }
    __syncthreads();
}

// ---------------------------------------------------------------------------
// Persistent fused ICP kernel.
// grid (SBLK=16, TSPLIT=4, BB=4) = 256 blocks x 256 threads, all co-resident.
// ---------------------------------------------------------------------------
__global__ void __launch_bounds__(256, 2)
icp_kernel(const float* __restrict__ src, const float* __restrict__ tgt,
           float* __restrict__ out) {
    __shared__ __align__(16) float tgP[CHUNK * 4];   // paired target layout
    __shared__ float  wsum[8][16];
    __shared__ double sums[BB][16];
    __shared__ float  Rsh[BB][12];
    __shared__ int    convf[BB];
    __shared__ int    s_isfin;
    __shared__ int    s_done;

    const int tid = threadIdx.x;
    const int bx = blockIdx.x, cy = blockIdx.y, b = blockIdx.z;
    const int n   = bx * 256 + tid;
    const int idx = b * NPTS + n;

    // ---- stage this block's target chunk once, paired layout:
    // pair p: [x0 x1 y0 y1 z0 z1 w0 w1]  (w = |t|^2)
    {
        const float* T = tgt + (size_t)(b * MPTS + cy * CHUNK) * 3;
        for (int k = tid; k < CHUNK; k += 256) {
            float x = T[3 * k], y = T[3 * k + 1], z = T[3 * k + 2];
            float w = fmaf(x, x, fmaf(y, y, z * z));
            int p = k >> 1, h = k & 1;
            tgP[p * 8 + 0 + h] = x;
            tgP[p * 8 + 2 + h] = y;
            tgP[p * 8 + 4 + h] = z;
            tgP[p * 8 + 6 + h] = w;
        }
    }
    __syncthreads();
    const unsigned tg_base = (unsigned)__cvta_generic_to_shared(tgP);

    for (int k = 0; k < ICP_STEPS; ++k) {
        // ---- wait for generation k (g_Rt + own g_temp published)
        if (k > 0) {
            if (tid == 0) {
                while (*(volatile unsigned*)&g_gen < (unsigned)k) __nanosleep(64);
                __threadfence();
            }
            __syncthreads();
        }

        // ---- transform for this step
        float Rt[12];
        if (k == 0) {
            Rt[0] = 1.f; Rt[1] = 0.f; Rt[2] = 0.f;
            Rt[3] = 0.f; Rt[4] = 1.f; Rt[5] = 0.f;
            Rt[6] = 0.f; Rt[7] = 0.f; Rt[8] = 1.f;
            Rt[9] = 0.f; Rt[10] = 0.f; Rt[11] = 0.f;
        } else {
#pragma unroll
            for (int q = 0; q < 12; ++q) Rt[q] = g_Rt[b][q];
        }

        // ---- own source point (iteration 0 reads the input directly)
        float px, py, pz;
        if (k == 0) { px = src[3 * idx]; py = src[3 * idx + 1]; pz = src[3 * idx + 2]; }
        else        { px = g_temp[3 * idx]; py = g_temp[3 * idx + 1]; pz = g_temp[3 * idx + 2]; }
        float wx, wy, wz;
        xform(Rt, px, py, pz, wx, wy, wz);

        // ---- NN phase over this block's chunk (packed f32x2, bit-identical
        //      per-half to the scalar fmaf chain; ascending-j strict-< argmin)
        const unsigned long long ax2 = pk2(-2.f * wx);
        const unsigned long long ay2 = pk2(-2.f * wy);
        const unsigned long long az2 = pk2(-2.f * wz);

        float smin = 3.4e38f;
        int   jb   = 0;
#pragma unroll 4
        for (int p = 0; p < CHUNK / 2; ++p) {
            unsigned addr = tg_base + p * 32;
            unsigned long long x01, y01, z01, w01;
            asm("ld.shared.v2.u64 {%0, %1}, [%2];"
                : "=l"(x01), "=l"(y01) : "r"(addr));
            asm("ld.shared.v2.u64 {%0, %1}, [%2];"
                : "=l"(z01), "=l"(w01) : "r"(addr + 16));
            unsigned long long s01 = fma2(az2, z01, w01);
            s01 = fma2(ay2, y01, s01);
            s01 = fma2(ax2, x01, s01);
            float s0, s1;
            upk2(s01, s0, s1);
            if (s0 < smin) { smin = s0; jb = 2 * p; }
            if (s1 < smin) { smin = s1; jb = 2 * p + 1; }
        }
        const unsigned long long mykey =
            ((unsigned long long)fmono(smin) << 16) | (unsigned)(cy * CHUNK + jb);

        if (cy != 0) {
            // publish candidate, signal group, next iteration
            g_cand[cy][idx] = mykey;
            __threadfence();
            __syncthreads();
            if (tid == 0) atomicAdd(&g_grp[b][bx], 1u);
            continue;
        }

        // =================== cy == 0 : MOM (+ maybe FIN) ====================
        if (tid == 0) {
            while (*(volatile unsigned*)&g_grp[b][bx] < 3u * (unsigned)(k + 1))
                __nanosleep(64);
            __threadfence();
        }
        __syncthreads();

        unsigned long long key = mykey;
        key = min(key, g_cand[1][idx]);
        key = min(key, g_cand[2][idx]);
        key = min(key, g_cand[3][idx]);
        const unsigned j = (unsigned)(key & 0xFFFFu);
        const float    s = fmono_inv((unsigned int)(key >> 16));

        // write back transformed cloud (wx.. identical to NN-phase arithmetic)
        g_temp[3 * idx] = wx; g_temp[3 * idx + 1] = wy; g_temp[3 * idx + 2] = wz;

        const float a2 = fmaf(wx, wx, fmaf(wy, wy, wz * wz));
        const float d2 = fmaxf(s + a2, 0.f);
        const float ec = sqrtf(d2);

        const float* tp = tgt + (size_t)(b * MPTS + j) * 3;
        const float tx = tp[0], ty = tp[1], tz = tp[2];

        const float v[16] = { wx, wy, wz, tx, ty, tz,
                              wx * tx, wx * ty, wx * tz,
                              wy * tx, wy * ty, wy * tz,
                              wz * tx, wz * ty, wz * tz, ec };
        block_reduce16(wsum, v, b, bx);

        __threadfence();
        __syncthreads();
        if (tid == 0) {
            unsigned old = atomicAdd(&g_momcnt, 1u);
            s_isfin = (old == (unsigned)(NMOM * (k + 1) - 1)) ? 1 : 0;
        }
        __syncthreads();

        if (s_isfin) {
            // ---- FIN: last-arriving mom block finalizes the step
            if (tid == 0) __threadfence();
            __syncthreads();
            if (tid < BB * 16) {
                const int bb = tid >> 4, q = tid & 15;
                double acc = 0.0;
                for (int blk = 0; blk < SBLK; ++blk)
                    acc += (double)g_part[bb][blk][q];
                sums[bb][q] = acc;
            }
            __syncthreads();

            double errnew = 0.0;
            if (tid < BB) {
                errnew = sums[tid][15] / (double)NPTS;
                const double errlast = (k == 0) ? 0.0 : g_errlast[tid];
                convf[tid] = (fabs(errnew - errlast) < ICP_TOL) ? 1 : 0;
                kabsch_sums(sums[tid], Rsh[tid]);
            }
            __syncthreads();
            if (tid == 0) {
                const int all  = convf[0] & convf[1] & convf[2] & convf[3];
                const int prev = (k == 0) ? 0 : g_done;
                s_done = prev | all;
                g_done = s_done;
            }
            __syncthreads();
            if (tid < BB) {
                if (!s_done) {
                    g_errlast[tid] = errnew;
                    for (int q = 0; q < 12; ++q) g_Rt[tid][q] = Rsh[tid][q];
                } else {
                    for (int q = 0; q < 12; ++q)
                        g_Rt[tid][q] = (q == 0 || q == 4 || q == 8) ? 1.f : 0.f;
                }
            }
            __threadfence();
            __syncthreads();
            if (tid == 0) atomicExch(&g_gen, (unsigned)(k + 1));   // release
        }
    }

    // ======================= FINAL kabsch(source, temporal) ==================
    if (cy != 0) return;   // non-mom blocks are done

    if (tid == 0) {
        while (*(volatile unsigned*)&g_gen < (unsigned)ICP_STEPS) __nanosleep(64);
        __threadfence();
    }
    __syncthreads();

    {
        float Rt[12];
#pragma unroll
        for (int q = 0; q < 12; ++q) Rt[q] = g_Rt[b][q];

        const float px = g_temp[3 * idx], py = g_temp[3 * idx + 1], pz = g_temp[3 * idx + 2];
        float wx, wy, wz;
        xform(Rt, px, py, pz, wx, wy, wz);

        const float sx = src[3 * idx], sy = src[3 * idx + 1], sz = src[3 * idx + 2];
        const float v[16] = { sx, sy, sz, wx, wy, wz,
                              sx * wx, sx * wy, sx * wz,
                              sy * wx, sy * wy, sy * wz,
                              sz * wx, sz * wy, sz * wz, 0.f };
        block_reduce16(wsum, v, b, bx);
    }

    __threadfence();
    __syncthreads();
    if (tid == 0) {
        unsigned old = atomicAdd(&g_momcnt, 1u);
        s_isfin = (old == (unsigned)(NMOM * (ICP_STEPS + 1) - 1)) ? 1 : 0;
    }
    __syncthreads();
    if (!s_isfin) return;

    // ---- last block: final kabsch, output, counter reset for next replay
    if (tid == 0) __threadfence();
    __syncthreads();
    if (tid < BB * 16) {
        const int bb = tid >> 4, q = tid & 15;
        double acc = 0.0;
        for (int blk = 0; blk < SBLK; ++blk) acc += (double)g_part[bb][blk][q];
        sums[bb][q] = acc;
    }
    __syncthreads();
    if (tid < BB) kabsch_sums(sums[tid], Rsh[tid]);
    __syncthreads();

    if (tid < BB * 12) {
        const int bb = tid / 12, q = tid % 12;
        const int i = q / 4, jj = q % 4;
        float val = (jj < 3) ? Rsh[bb][3 * i + jj] : Rsh[bb][9 + i];
        out[bb * 12 + i * 4 + jj] = val;
    }

    // reset control state so every graph replay starts clean
    if (tid == 0) { g_gen = 0u; g_momcnt = 0u; }
    if (tid < BB * SBLK) ((unsigned*)g_grp)[tid] = 0u;
}

// ---------------------------------------------------------------------------
extern "C" void kernel_launch(void* const* d_in, const int* in_sizes, int n_in,
                              void* d_out, int out_size) {
    const float* source = (const float*)d_in[0];
    const float* target = (const float*)d_in[1];
    float*       out    = (float*)d_out;

    icp_kernel<<<dim3(SBLK, TSPLIT, BB), 256>>>(source, target, out);
}

// round 4
// speedup vs baseline: 1.0341x; 1.0341x over previous
#include <cuda_runtime.h>
#include <math.h>

// Problem constants (from reference setup_inputs)
#define BB      4
#define NPTS    4096
#define MPTS    4096
#define TSPLIT  4
#define CHUNK   (MPTS / TSPLIT)   // 1024 targets per chunk
#define NPAIR   (CHUNK / 2)       // 512 pairs
#define NSTR    4                 // independent argmin streams per thread
#define PPS     (NPAIR / NSTR)    // 128 pairs per stream
#define SBLK    (NPTS / 256)      // 16 source blocks per batch
#define ICP_STEPS 16
#define ICP_TOL   1e-6
#define NMOM    (SBLK * BB)       // 64 mom-capable blocks

// ---------------------------------------------------------------------------
// Device-global scratch. Control counters are monotonic within a launch and
// reset by the final block -> replay-clean for CUDA graphs.
// ---------------------------------------------------------------------------
__device__ float               g_temp[BB * NPTS * 3];
__device__ unsigned long long  g_cand[TSPLIT][BB * NPTS];
__device__ float               g_part[BB][SBLK][16];
__device__ float               g_Rt[BB][12];
__device__ double              g_errlast[BB];
__device__ int                 g_done;
__device__ unsigned            g_gen;
__device__ unsigned            g_momcnt;
__device__ unsigned            g_grp[BB][SBLK];

// ---------------------------------------------------------------------------
__device__ __forceinline__ void xform(const float* Mtx,
                                      float px, float py, float pz,
                                      float& qx, float& qy, float& qz) {
    qx = fmaf(Mtx[0], px, fmaf(Mtx[1], py, fmaf(Mtx[2], pz, Mtx[9])));
    qy = fmaf(Mtx[3], px, fmaf(Mtx[4], py, fmaf(Mtx[5], pz, Mtx[10])));
    qz = fmaf(Mtx[6], px, fmaf(Mtx[7], py, fmaf(Mtx[8], pz, Mtx[11])));
}

__device__ __forceinline__ unsigned int fmono(float f) {
    unsigned int b = __float_as_uint(f);
    return (b & 0x80000000u) ? ~b : (b | 0x80000000u);
}
__device__ __forceinline__ float fmono_inv(unsigned int m) {
    unsigned int b = (m & 0x80000000u) ? (m ^ 0x80000000u) : ~m;
    return __uint_as_float(b);
}

// packed f32x2 helpers (per-half rounding identical to scalar FFMA)
__device__ __forceinline__ unsigned long long pk2(float v) {
    unsigned long long r;
    asm("mov.b64 %0, {%1, %1};" : "=l"(r) : "f"(v));
    return r;
}
__device__ __forceinline__ unsigned long long fma2(unsigned long long a,
                                                   unsigned long long b,
                                                   unsigned long long c) {
    unsigned long long d;
    asm("fma.rn.f32x2 %0, %1, %2, %3;" : "=l"(d) : "l"(a), "l"(b), "l"(c));
    return d;
}
__device__ __forceinline__ void upk2(unsigned long long v, float& lo, float& hi) {
    asm("mov.b64 {%0, %1}, %2;" : "=f"(lo), "=f"(hi) : "l"(v));
}

// ---------------------------------------------------------------------------
// Kabsch from accumulated sums (identical arithmetic to R2/R3).
// ---------------------------------------------------------------------------
__device__ void kabsch_sums(const double* S, float* Rt) {
    const double invN = 1.0 / (double)NPTS;
    double cs[3] = { S[0] * invN, S[1] * invN, S[2] * invN };
    double ct[3] = { S[3] * invN, S[4] * invN, S[5] * invN };

    float H[3][3];
    for (int i = 0; i < 3; ++i)
        for (int j = 0; j < 3; ++j)
            H[i][j] = (float)(S[6 + 3 * i + j] - (double)NPTS * cs[i] * ct[j]);

    float A[3][3];
    for (int i = 0; i < 3; ++i)
        for (int j = 0; j < 3; ++j)
            A[i][j] = H[0][i] * H[0][j] + H[1][i] * H[1][j] + H[2][i] * H[2][j];

    float V[3][3] = { {1,0,0},{0,1,0},{0,0,1} };
    const float diagmag = fabsf(A[0][0]) + fabsf(A[1][1]) + fabsf(A[2][2]);
    const float offeps  = diagmag * 1e-9f;
    for (int sweep = 0; sweep < 8; ++sweep) {
        const float off = fabsf(A[0][1]) + fabsf(A[0][2]) + fabsf(A[1][2]);
        if (off <= offeps) break;
        for (int pq = 0; pq < 3; ++pq) {
            const int p = (pq == 2) ? 1 : 0;
            const int q = (pq == 0) ? 1 : 2;
            const float apq = A[p][q];
            if (fabsf(apq) <= 0.0f) continue;
            const float theta = (A[q][q] - A[p][p]) / (2.0f * apq);
            const float tt = ((theta >= 0.0f) ? 1.0f : -1.0f) /
                             (fabsf(theta) + sqrtf(theta * theta + 1.0f));
            const float c = rsqrtf(tt * tt + 1.0f);
            const float s = tt * c;
            for (int k = 0; k < 3; ++k) { float a1 = A[p][k], a2 = A[q][k];
                A[p][k] = c * a1 - s * a2; A[q][k] = s * a1 + c * a2; }
            for (int k = 0; k < 3; ++k) { float a1 = A[k][p], a2 = A[k][q];
                A[k][p] = c * a1 - s * a2; A[k][q] = s * a1 + c * a2; }
            for (int k = 0; k < 3; ++k) { float v1 = V[k][p], v2 = V[k][q];
                V[k][p] = c * v1 - s * v2; V[k][q] = s * v1 + c * v2; }
        }
    }

    int id[3] = { 0, 1, 2 };
    float w[3] = { A[0][0], A[1][1], A[2][2] };
    if (w[id[0]] < w[id[1]]) { int t0 = id[0]; id[0] = id[1]; id[1] = t0; }
    if (w[id[0]] < w[id[2]]) { int t0 = id[0]; id[0] = id[2]; id[2] = t0; }
    if (w[id[1]] < w[id[2]]) { int t0 = id[1]; id[1] = id[2]; id[2] = t0; }

    float v1[3], v2[3], v3[3];
    for (int k = 0; k < 3; ++k) { v1[k] = V[k][id[0]]; v2[k] = V[k][id[1]]; v3[k] = V[k][id[2]]; }

    float u1[3], u2[3], u3[3];
    for (int i = 0; i < 3; ++i) u1[i] = H[i][0] * v1[0] + H[i][1] * v1[1] + H[i][2] * v1[2];
    {
        float n1 = u1[0]*u1[0] + u1[1]*u1[1] + u1[2]*u1[2];
        float r = (n1 > 0.0f) ? rsqrtf(n1) : 0.0f;
        u1[0] *= r; u1[1] *= r; u1[2] *= r;
    }
    for (int i = 0; i < 3; ++i) u2[i] = H[i][0] * v2[0] + H[i][1] * v2[1] + H[i][2] * v2[2];
    {
        float pr = u1[0]*u2[0] + u1[1]*u2[1] + u1[2]*u2[2];
        u2[0] -= pr * u1[0]; u2[1] -= pr * u1[1]; u2[2] -= pr * u1[2];
        float n2 = u2[0]*u2[0] + u2[1]*u2[1] + u2[2]*u2[2];
        float r = (n2 > 0.0f) ? rsqrtf(n2) : 0.0f;
        u2[0] *= r; u2[1] *= r; u2[2] *= r;
    }
    u3[0] = u1[1]*u2[2] - u1[2]*u2[1];
    u3[1] = u1[2]*u2[0] - u1[0]*u2[2];
    u3[2] = u1[0]*u2[1] - u1[1]*u2[0];

    const float d =
        v1[0] * (v2[1]*v3[2] - v2[2]*v3[1]) -
        v1[1] * (v2[0]*v3[2] - v2[2]*v3[0]) +
        v1[2] * (v2[0]*v3[1] - v2[1]*v3[0]);

    float R[9];
    for (int i = 0; i < 3; ++i)
        for (int j = 0; j < 3; ++j)
            R[3 * i + j] = v1[i]*u1[j] + v2[i]*u2[j] + d * v3[i]*u3[j];
    for (int k = 0; k < 9; ++k) Rt[k] = R[k];
    for (int i = 0; i < 3; ++i)
        Rt[9 + i] = (float)ct[i] - (R[3*i]*(float)cs[0] + R[3*i+1]*(float)cs[1]
                                    + R[3*i+2]*(float)cs[2]);
}

// ---------------------------------------------------------------------------
__device__ __forceinline__ void block_reduce16(float wsum[8][16],
                                               const float v[16], int b, int blk) {
    const int lane = threadIdx.x & 31, wid = threadIdx.x >> 5;
#pragma unroll
    for (int q = 0; q < 16; ++q) {
        float r = v[q];
#pragma unroll
        for (int o = 16; o > 0; o >>= 1) r += __shfl_down_sync(0xffffffffu, r, o);
        if (lane == 0) wsum[wid][q] = r;
    }
    __syncthreads();
    if (threadIdx.x < 16) {
        float acc = 0.f;
#pragma unroll
        for (int w = 0; w < 8; ++w) acc += wsum[w][threadIdx.x];
        g_part[b][blk][threadIdx.x] = acc;
    }
    __syncthreads();
}

// ---------------------------------------------------------------------------
// Persistent fused ICP kernel.
// grid (SBLK=16, TSPLIT=4, BB=4) = 256 blocks x 256 threads, all co-resident.
// ---------------------------------------------------------------------------
__global__ void __launch_bounds__(256, 2)
icp_kernel(const float* __restrict__ src, const float* __restrict__ tgt,
           float* __restrict__ out) {
    __shared__ __align__(16) float tgP[CHUNK * 4];   // paired target layout
    __shared__ float  wsum[8][16];
    __shared__ double sums[BB][16];
    __shared__ float  Rsh[BB][12];
    __shared__ int    convf[BB];
    __shared__ int    s_isfin;
    __shared__ int    s_done;

    const int tid = threadIdx.x;
    const int bx = blockIdx.x, cy = blockIdx.y, b = blockIdx.z;
    const int n   = bx * 256 + tid;
    const int idx = b * NPTS + n;

    // stage this block's target chunk once; pair p: [x0 x1 y0 y1 z0 z1 w0 w1]
    {
        const float* T = tgt + (size_t)(b * MPTS + cy * CHUNK) * 3;
        for (int k = tid; k < CHUNK; k += 256) {
            float x = T[3 * k], y = T[3 * k + 1], z = T[3 * k + 2];
            float w = fmaf(x, x, fmaf(y, y, z * z));
            int p = k >> 1, h = k & 1;
            tgP[p * 8 + 0 + h] = x;
            tgP[p * 8 + 2 + h] = y;
            tgP[p * 8 + 4 + h] = z;
            tgP[p * 8 + 6 + h] = w;
        }
    }
    __syncthreads();
    const unsigned tg_base = (unsigned)__cvta_generic_to_shared(tgP);

    for (int k = 0; k < ICP_STEPS; ++k) {
        if (k > 0) {
            if (tid == 0) {
                while (*(volatile unsigned*)&g_gen < (unsigned)k) __nanosleep(64);
                __threadfence();
            }
            __syncthreads();
        }

        float Rt[12];
        if (k == 0) {
            Rt[0] = 1.f; Rt[1] = 0.f; Rt[2] = 0.f;
            Rt[3] = 0.f; Rt[4] = 1.f; Rt[5] = 0.f;
            Rt[6] = 0.f; Rt[7] = 0.f; Rt[8] = 1.f;
            Rt[9] = 0.f; Rt[10] = 0.f; Rt[11] = 0.f;
        } else {
#pragma unroll
            for (int q = 0; q < 12; ++q) Rt[q] = g_Rt[b][q];
        }

        float px, py, pz;
        if (k == 0) { px = src[3 * idx]; py = src[3 * idx + 1]; pz = src[3 * idx + 2]; }
        else        { px = g_temp[3 * idx]; py = g_temp[3 * idx + 1]; pz = g_temp[3 * idx + 2]; }
        float wx, wy, wz;
        xform(Rt, px, py, pz, wx, wy, wz);

        // ---- NN phase: 4 independent argmin streams over contiguous
        //      quarter-ranges of the chunk. Bit-identical distances; merge
        //      in ascending stream order with strict < reproduces the exact
        //      ascending-j strict-< argmin (incl. tie-breaks).
        const unsigned long long ax2 = pk2(-2.f * wx);
        const unsigned long long ay2 = pk2(-2.f * wy);
        const unsigned long long az2 = pk2(-2.f * wz);

        float smin0 = 3.4e38f, smin1 = 3.4e38f, smin2 = 3.4e38f, smin3 = 3.4e38f;
        int   jb0 = 0, jb1 = 0, jb2 = 0, jb3 = 0;

#pragma unroll 2
        for (int i = 0; i < PPS; ++i) {
            const unsigned a0 = tg_base + (unsigned)(i) * 32u;
            const unsigned a1 = a0 + (unsigned)(PPS) * 32u;
            const unsigned a2 = a0 + (unsigned)(2 * PPS) * 32u;
            const unsigned a3 = a0 + (unsigned)(3 * PPS) * 32u;

            unsigned long long x0, y0, z0, w0, x1, y1, z1, w1;
            unsigned long long x2, y2, z2, w2, x3, y3, z3, w3;
            asm("ld.shared.v2.u64 {%0, %1}, [%2];" : "=l"(x0), "=l"(y0) : "r"(a0));
            asm("ld.shared.v2.u64 {%0, %1}, [%2];" : "=l"(z0), "=l"(w0) : "r"(a0 + 16));
            asm("ld.shared.v2.u64 {%0, %1}, [%2];" : "=l"(x1), "=l"(y1) : "r"(a1));
            asm("ld.shared.v2.u64 {%0, %1}, [%2];" : "=l"(z1), "=l"(w1) : "r"(a1 + 16));
            asm("ld.shared.v2.u64 {%0, %1}, [%2];" : "=l"(x2), "=l"(y2) : "r"(a2));
            asm("ld.shared.v2.u64 {%0, %1}, [%2];" : "=l"(z2), "=l"(w2) : "r"(a2 + 16));
            asm("ld.shared.v2.u64 {%0, %1}, [%2];" : "=l"(x3), "=l"(y3) : "r"(a3));
            asm("ld.shared.v2.u64 {%0, %1}, [%2];" : "=l"(z3), "=l"(w3) : "r"(a3 + 16));

            unsigned long long s0 = fma2(ax2, x0, fma2(ay2, y0, fma2(az2, z0, w0)));
            unsigned long long s1 = fma2(ax2, x1, fma2(ay2, y1, fma2(az2, z1, w1)));
            unsigned long long s2 = fma2(ax2, x2, fma2(ay2, y2, fma2(az2, z2, w2)));
            unsigned long long s3 = fma2(ax2, x3, fma2(ay2, y3, fma2(az2, z3, w3)));

            float e0, o0, e1, o1, e2, o2, e3, o3;
            upk2(s0, e0, o0); upk2(s1, e1, o1); upk2(s2, e2, o2); upk2(s3, e3, o3);

            if (e0 < smin0) { smin0 = e0; jb0 = 2 * i; }
            if (o0 < smin0) { smin0 = o0; jb0 = 2 * i + 1; }
            if (e1 < smin1) { smin1 = e1; jb1 = 2 * i; }
            if (o1 < smin1) { smin1 = o1; jb1 = 2 * i + 1; }
            if (e2 < smin2) { smin2 = e2; jb2 = 2 * i; }
            if (o2 < smin2) { smin2 = o2; jb2 = 2 * i + 1; }
            if (e3 < smin3) { smin3 = e3; jb3 = 2 * i; }
            if (o3 < smin3) { smin3 = o3; jb3 = 2 * i + 1; }
        }

        // merge streams in ascending j order with strict <
        float smin = smin0;
        int   jb   = jb0;                      // stream 0: j = jb0
        if (smin1 < smin) { smin = smin1; jb = 2 * PPS + jb1; }
        if (smin2 < smin) { smin = smin2; jb = 4 * PPS + jb2; }
        if (smin3 < smin) { smin = smin3; jb = 6 * PPS + jb3; }

        const unsigned long long mykey =
            ((unsigned long long)fmono(smin) << 16) | (unsigned)(cy * CHUNK + jb);

        if (cy != 0) {
            g_cand[cy][idx] = mykey;
            __threadfence();
            __syncthreads();
            if (tid == 0) atomicAdd(&g_grp[b][bx], 1u);
            continue;
        }

        // =================== cy == 0 : MOM (+ maybe FIN) ====================
        if (tid == 0) {
            while (*(volatile unsigned*)&g_grp[b][bx] < 3u * (unsigned)(k + 1))
                __nanosleep(64);
            __threadfence();
        }
        __syncthreads();

        unsigned long long key = mykey;
        key = min(key, g_cand[1][idx]);
        key = min(key, g_cand[2][idx]);
        key = min(key, g_cand[3][idx]);
        const unsigned j = (unsigned)(key & 0xFFFFu);
        const float    s = fmono_inv((unsigned int)(key >> 16));

        g_temp[3 * idx] = wx; g_temp[3 * idx + 1] = wy; g_temp[3 * idx + 2] = wz;

        const float a2v = fmaf(wx, wx, fmaf(wy, wy, wz * wz));
        const float d2  = fmaxf(s + a2v, 0.f);
        const float ec  = sqrtf(d2);

        const float* tp = tgt + (size_t)(b * MPTS + j) * 3;
        const float tx = tp[0], ty = tp[1], tz = tp[2];

        const float v[16] = { wx, wy, wz, tx, ty, tz,
                              wx * tx, wx * ty, wx * tz,
                              wy * tx, wy * ty, wy * tz,
                              wz * tx, wz * ty, wz * tz, ec };
        block_reduce16(wsum, v, b, bx);

        __threadfence();
        __syncthreads();
        if (tid == 0) {
            unsigned old = atomicAdd(&g_momcnt, 1u);
            s_isfin = (old == (unsigned)(NMOM * (k + 1) - 1)) ? 1 : 0;
        }
        __syncthreads();

        if (s_isfin) {
            if (tid == 0) __threadfence();
            __syncthreads();
            if (tid < BB * 16) {
                const int bb = tid >> 4, q = tid & 15;
                double acc = 0.0;
                for (int blk = 0; blk < SBLK; ++blk)
                    acc += (double)g_part[bb][blk][q];
                sums[bb][q] = acc;
            }
            __syncthreads();

            double errnew = 0.0;
            if (tid < BB) {
                errnew = sums[tid][15] / (double)NPTS;
                const double errlast = (k == 0) ? 0.0 : g_errlast[tid];
                convf[tid] = (fabs(errnew - errlast) < ICP_TOL) ? 1 : 0;
                kabsch_sums(sums[tid], Rsh[tid]);
            }
            __syncthreads();
            if (tid == 0) {
                const int all  = convf[0] & convf[1] & convf[2] & convf[3];
                const int prev = (k == 0) ? 0 : g_done;
                s_done = prev | all;
                g_done = s_done;
            }
            __syncthreads();
            if (tid < BB) {
                if (!s_done) {
                    g_errlast[tid] = errnew;
                    for (int q = 0; q < 12; ++q) g_Rt[tid][q] = Rsh[tid][q];
                } else {
                    for (int q = 0; q < 12; ++q)
                        g_Rt[tid][q] = (q == 0 || q == 4 || q == 8) ? 1.f : 0.f;
                }
            }
            __threadfence();
            __syncthreads();
            if (tid == 0) atomicExch(&g_gen, (unsigned)(k + 1));
        }
    }

    // ======================= FINAL kabsch(source, temporal) ==================
    if (cy != 0) return;

    if (tid == 0) {
        while (*(volatile unsigned*)&g_gen < (unsigned)ICP_STEPS) __nanosleep(64);
        __threadfence();
    }
    __syncthreads();

    {
        float Rt[12];
#pragma unroll
        for (int q = 0; q < 12; ++q) Rt[q] = g_Rt[b][q];

        const float px = g_temp[3 * idx], py = g_temp[3 * idx + 1], pz = g_temp[3 * idx + 2];
        float wx, wy, wz;
        xform(Rt, px, py, pz, wx, wy, wz);

        const float sx = src[3 * idx], sy = src[3 * idx + 1], sz = src[3 * idx + 2];
        const float v[16] = { sx, sy, sz, wx, wy, wz,
                              sx * wx, sx * wy, sx * wz,
                              sy * wx, sy * wy, sy * wz,
                              sz * wx, sz * wy, sz * wz, 0.f };
        block_reduce16(wsum, v, b, bx);
    }

    __threadfence();
    __syncthreads();
    if (tid == 0) {
        unsigned old = atomicAdd(&g_momcnt, 1u);
        s_isfin = (old == (unsigned)(NMOM * (ICP_STEPS + 1) - 1)) ? 1 : 0;
    }
    __syncthreads();
    if (!s_isfin) return;

    if (tid == 0) __threadfence();
    __syncthreads();
    if (tid < BB * 16) {
        const int bb = tid >> 4, q = tid & 15;
        double acc = 0.0;
        for (int blk = 0; blk < SBLK; ++blk) acc += (double)g_part[bb][blk][q];
        sums[bb][q] = acc;
    }
    __syncthreads();
    if (tid < BB) kabsch_sums(sums[tid], Rsh[tid]);
    __syncthreads();

    if (tid < BB * 12) {
        const int bb = tid / 12, q = tid % 12;
        const int i = q / 4, jj = q % 4;
        float val = (jj < 3) ? Rsh[bb][3 * i + jj] : Rsh[bb][9 + i];
        out[bb * 12 + i * 4 + jj] = val;
    }

    if (tid == 0) { g_gen = 0u; g_momcnt = 0u; }
    if (tid < BB * SBLK) ((unsigned*)g_grp)[tid] = 0u;
}

// ---------------------------------------------------------------------------
extern "C" void kernel_launch(void* const* d_in, const int* in_sizes, int n_in,
                              void* d_out, int out_size) {
    const float* source = (const float*)d_in[0];
    const float* target = (const float*)d_in[1];
    float*       out    = (float*)d_out;

    icp_kernel<<<dim3(SBLK, TSPLIT, BB), 256>>>(source, target, out);
}